// round 1
// baseline (speedup 1.0000x reference)
#include <cuda_runtime.h>

// Problem shape (fixed by setup_inputs)
#define B_  4
#define H_  16
#define S_  2048
#define D_  64

#define QT      16        // q rows per CTA
#define KT      128       // k rows per staged tile
#define NKT     (S_ / KT) // 16 tiles
#define THREADS 256
#define KROW    68        // padded smem row stride (floats): 272B, stride mod 128 = 16 -> conflict-free LDS128
#define NEG_INF_F (-1e14f)

// dynamic smem layout (floats):
//   Ss[QT][S_]      = 32768 floats (131072 B)  score / prob tile
//   Ks[KT][KROW]    =  8704 floats ( 34816 B)  K tile / V tile / reduction scratch
//   Qs[QT][D_]      =  1024 floats (  4096 B)
#define SMEM_FLOATS (QT * S_ + KT * KROW + QT * D_)
#define SMEM_BYTES  (SMEM_FLOATS * 4)

__global__ __launch_bounds__(THREADS, 1)
void attn_fused(const float* __restrict__ Q, const float* __restrict__ K,
                const float* __restrict__ V, const int* __restrict__ mask,
                float* __restrict__ out, float* __restrict__ attn)
{
    extern __shared__ float smem[];
    float* Ss = smem;                 // QT * S_
    float* Ks = smem + QT * S_;       // KT * KROW
    float* Qs = Ks + KT * KROW;       // QT * D_

    const int tid = threadIdx.x;
    const int bh  = blockIdx.x;       // b*H + h
    const int b   = bh >> 4;          // H_ == 16
    const int q0  = blockIdx.y * QT;

    const float* Qbh = Q + (size_t)bh * S_ * D_ + (size_t)q0 * D_;
    const float* Kbh = K + (size_t)bh * S_ * D_;
    const float* Vbh = V + (size_t)bh * S_ * D_;

    // ---- stage Q tile: QT*D_ = 1024 floats = 256 float4 ----
    ((float4*)Qs)[tid] = ((const float4*)Qbh)[tid];
    __syncthreads();

    // ======================= Phase 1: S = (Q K^T) * scale =======================
    {
        const int kx = tid & 31;   // 32 k-lanes, k = kx + 32*j
        const int qy = tid >> 5;   // 8 q-pairs: rows qy and qy+8

        for (int kt = 0; kt < NKT; ++kt) {
            // stage K tile KT x D_ (coalesced float4 loads)
            {
                const float4* src = (const float4*)(Kbh + (size_t)kt * KT * D_);
                #pragma unroll
                for (int t = 0; t < 8; ++t) {
                    int idx = tid + t * THREADS;      // 0..2047 float4s
                    int r = idx >> 4, c4 = idx & 15;
                    *(float4*)(Ks + r * KROW + c4 * 4) = src[idx];
                }
            }
            __syncthreads();

            float acc0[4] = {0.f, 0.f, 0.f, 0.f};
            float acc1[4] = {0.f, 0.f, 0.f, 0.f};
            #pragma unroll
            for (int d4 = 0; d4 < 16; ++d4) {
                float4 qa = *(const float4*)(Qs + (qy    ) * D_ + d4 * 4); // broadcast
                float4 qb = *(const float4*)(Qs + (qy + 8) * D_ + d4 * 4); // broadcast
                #pragma unroll
                for (int j = 0; j < 4; ++j) {
                    float4 kv = *(const float4*)(Ks + (kx + 32 * j) * KROW + d4 * 4);
                    acc0[j] += qa.x * kv.x + qa.y * kv.y + qa.z * kv.z + qa.w * kv.w;
                    acc1[j] += qb.x * kv.x + qb.y * kv.y + qb.z * kv.z + qb.w * kv.w;
                }
            }
            const float scale = 0.125f; // 1/sqrt(64)
            #pragma unroll
            for (int j = 0; j < 4; ++j) {
                Ss[(qy    ) * S_ + kt * KT + kx + 32 * j] = acc0[j] * scale;
                Ss[(qy + 8) * S_ + kt * KT + kx + 32 * j] = acc1[j] * scale;
            }
            __syncthreads();   // Ks reuse next tile
        }
    }

    // ======================= Phase 2: mask + softmax (per row) =======================
    // 16-lane team per q row; teams are exact half-warps.
    {
        const int tx = tid & 15;
        const int ty = tid >> 4;
        const int*  mrow = mask + ((size_t)b * S_ + (q0 + ty)) * S_;
        float*      srow = Ss + ty * S_;

        float mx = NEG_INF_F;
        for (int j = tx; j < S_; j += 16) {
            float s = (mrow[j] == 0) ? NEG_INF_F : srow[j];
            srow[j] = s;
            mx = fmaxf(mx, s);
        }
        #pragma unroll
        for (int o = 8; o; o >>= 1) mx = fmaxf(mx, __shfl_xor_sync(0xffffffffu, mx, o));

        float sum = 0.f;
        for (int j = tx; j < S_; j += 16) {
            float e = __expf(srow[j] - mx);
            srow[j] = e;
            sum += e;
        }
        #pragma unroll
        for (int o = 8; o; o >>= 1) sum += __shfl_xor_sync(0xffffffffu, sum, o);
        const float inv = 1.0f / sum;

        if (attn) {
            float* arow = attn + ((size_t)bh * S_ + (q0 + ty)) * S_;
            for (int j = tx; j < S_; j += 16) {
                float p = srow[j] * inv;
                srow[j] = p;
                arow[j] = p;        // coalesced streaming store
            }
        } else {
            for (int j = tx; j < S_; j += 16) srow[j] *= inv;
        }
    }
    __syncthreads();

    // ======================= Phase 3: out = P @ V (split-k x4) =======================
    {
        const int d4 = tid & 15;         // d = d4*4 .. d4*4+3
        const int qg = (tid >> 4) & 3;   // q group: rows qg*4 .. qg*4+3
        const int kp = tid >> 6;         // k partition 0..3 (32 k each per tile)

        float4 acc[4];
        #pragma unroll
        for (int qq = 0; qq < 4; ++qq) acc[qq] = make_float4(0.f, 0.f, 0.f, 0.f);

        for (int vt = 0; vt < NKT; ++vt) {
            __syncthreads();   // previous V tile fully consumed
            {
                const float4* src = (const float4*)(Vbh + (size_t)vt * KT * D_);
                #pragma unroll
                for (int t = 0; t < 8; ++t) {
                    int idx = tid + t * THREADS;
                    int r = idx >> 4, c4 = idx & 15;
                    *(float4*)(Ks + r * KROW + c4 * 4) = src[idx];
                }
            }
            __syncthreads();

            #pragma unroll 4
            for (int i = 0; i < 32; ++i) {
                const int kl = kp * 32 + i;
                float4 vv = *(const float4*)(Ks + kl * KROW + d4 * 4);
                #pragma unroll
                for (int qq = 0; qq < 4; ++qq) {
                    float p = Ss[(qg * 4 + qq) * S_ + vt * KT + kl]; // broadcast
                    acc[qq].x += p * vv.x;
                    acc[qq].y += p * vv.y;
                    acc[qq].z += p * vv.z;
                    acc[qq].w += p * vv.w;
                }
            }
        }

        // cross-partition reduction via smem (reuse Ks: 4 * 256 float4 = 16 KB)
        __syncthreads();
        float4* red = (float4*)Ks;
        #pragma unroll
        for (int qq = 0; qq < 4; ++qq)
            red[kp * 256 + (qg * 4 + qq) * 16 + d4] = acc[qq];
        __syncthreads();

        if (out) {
            // 256 threads, one (q, d4) pair each
            const int q  = tid >> 4;
            const int dd = tid & 15;
            float4 r0 = red[0 * 256 + q * 16 + dd];
            float4 r1 = red[1 * 256 + q * 16 + dd];
            float4 r2 = red[2 * 256 + q * 16 + dd];
            float4 r3 = red[3 * 256 + q * 16 + dd];
            float4 o;
            o.x = r0.x + r1.x + r2.x + r3.x;
            o.y = r0.y + r1.y + r2.y + r3.y;
            o.z = r0.z + r1.z + r2.z + r3.z;
            o.w = r0.w + r1.w + r2.w + r3.w;
            *(float4*)(out + ((size_t)bh * S_ + (q0 + q)) * D_ + dd * 4) = o;
        }
    }
}

extern "C" void kernel_launch(void* const* d_in, const int* in_sizes, int n_in,
                              void* d_out, int out_size)
{
    const float* Q    = (const float*)d_in[0];
    const float* K    = (const float*)d_in[1];
    const float* V    = (const float*)d_in[2];
    const int*   mask = (const int*)d_in[3];

    const size_t OUT_E  = (size_t)B_ * H_ * S_ * D_;   //   8388608
    const size_t ATTN_E = (size_t)B_ * H_ * S_ * S_;   // 268435456

    float* o = nullptr;
    float* a = nullptr;
    if ((size_t)out_size >= OUT_E + ATTN_E) {          // (out, attn) concatenated
        o = (float*)d_out;
        a = (float*)d_out + OUT_E;
    } else if ((size_t)out_size == ATTN_E) {           // only attn expected
        a = (float*)d_out;
    } else {                                           // only out expected
        o = (float*)d_out;
    }

    cudaFuncSetAttribute(attn_fused, cudaFuncAttributeMaxDynamicSharedMemorySize, SMEM_BYTES);

    dim3 grid(B_ * H_, S_ / QT);
    attn_fused<<<grid, THREADS, SMEM_BYTES>>>(Q, K, V, mask, o, a);
}

// round 2
// speedup vs baseline: 1.0001x; 1.0001x over previous
#include <cuda_runtime.h>

// Problem shape (fixed by setup_inputs)
#define B_  4
#define H_  16
#define S_  2048
#define D_  64

#define QT      16        // q rows per CTA
#define KT      128       // k rows per staged tile
#define NKT     (S_ / KT) // 16 tiles
#define THREADS 256
#define KROW    68        // padded smem row stride (floats): 272B, stride mod 128 = 16 -> conflict-free LDS128
#define NEG_INF_F (-1e14f)

// dynamic smem layout (floats):
//   Ss[QT][S_]      = 32768 floats (131072 B)  score / prob tile
//   Ks[KT][KROW]    =  8704 floats ( 34816 B)  K tile / V tile / reduction scratch
//   Qs[QT][D_]      =  1024 floats (  4096 B)
#define SMEM_FLOATS (QT * S_ + KT * KROW + QT * D_)
#define SMEM_BYTES  (SMEM_FLOATS * 4)

__global__ __launch_bounds__(THREADS, 1)
void attn_fused(const float* __restrict__ Q, const float* __restrict__ K,
                const float* __restrict__ V, const int* __restrict__ mask,
                float* __restrict__ out, float* __restrict__ attn)
{
    extern __shared__ float smem[];
    float* Ss = smem;                 // QT * S_
    float* Ks = smem + QT * S_;       // KT * KROW
    float* Qs = Ks + KT * KROW;       // QT * D_

    const int tid = threadIdx.x;
    const int bh  = blockIdx.x;       // b*H + h
    const int b   = bh >> 4;          // H_ == 16
    const int q0  = blockIdx.y * QT;

    const float* Qbh = Q + (size_t)bh * S_ * D_ + (size_t)q0 * D_;
    const float* Kbh = K + (size_t)bh * S_ * D_;
    const float* Vbh = V + (size_t)bh * S_ * D_;

    // ---- stage Q tile: QT*D_ = 1024 floats = 256 float4 ----
    ((float4*)Qs)[tid] = ((const float4*)Qbh)[tid];
    __syncthreads();

    // ======================= Phase 1: S = (Q K^T) * scale =======================
    {
        const int kx = tid & 31;   // 32 k-lanes, k = kx + 32*j
        const int qy = tid >> 5;   // 8 q-pairs: rows qy and qy+8

        for (int kt = 0; kt < NKT; ++kt) {
            // stage K tile KT x D_ (coalesced float4 loads)
            {
                const float4* src = (const float4*)(Kbh + (size_t)kt * KT * D_);
                #pragma unroll
                for (int t = 0; t < 8; ++t) {
                    int idx = tid + t * THREADS;      // 0..2047 float4s
                    int r = idx >> 4, c4 = idx & 15;
                    *(float4*)(Ks + r * KROW + c4 * 4) = src[idx];
                }
            }
            __syncthreads();

            float acc0[4] = {0.f, 0.f, 0.f, 0.f};
            float acc1[4] = {0.f, 0.f, 0.f, 0.f};
            #pragma unroll
            for (int d4 = 0; d4 < 16; ++d4) {
                float4 qa = *(const float4*)(Qs + (qy    ) * D_ + d4 * 4); // broadcast
                float4 qb = *(const float4*)(Qs + (qy + 8) * D_ + d4 * 4); // broadcast
                #pragma unroll
                for (int j = 0; j < 4; ++j) {
                    float4 kv = *(const float4*)(Ks + (kx + 32 * j) * KROW + d4 * 4);
                    acc0[j] += qa.x * kv.x + qa.y * kv.y + qa.z * kv.z + qa.w * kv.w;
                    acc1[j] += qb.x * kv.x + qb.y * kv.y + qb.z * kv.z + qb.w * kv.w;
                }
            }
            const float scale = 0.125f; // 1/sqrt(64)
            #pragma unroll
            for (int j = 0; j < 4; ++j) {
                Ss[(qy    ) * S_ + kt * KT + kx + 32 * j] = acc0[j] * scale;
                Ss[(qy + 8) * S_ + kt * KT + kx + 32 * j] = acc1[j] * scale;
            }
            __syncthreads();   // Ks reuse next tile
        }
    }

    // ======================= Phase 2: mask + softmax (per row) =======================
    // 16-lane team per q row; teams are exact half-warps.
    {
        const int tx = tid & 15;
        const int ty = tid >> 4;
        const int*  mrow = mask + ((size_t)b * S_ + (q0 + ty)) * S_;
        float*      srow = Ss + ty * S_;

        float mx = NEG_INF_F;
        for (int j = tx; j < S_; j += 16) {
            float s = (mrow[j] == 0) ? NEG_INF_F : srow[j];
            srow[j] = s;
            mx = fmaxf(mx, s);
        }
        #pragma unroll
        for (int o = 8; o; o >>= 1) mx = fmaxf(mx, __shfl_xor_sync(0xffffffffu, mx, o));

        float sum = 0.f;
        for (int j = tx; j < S_; j += 16) {
            float e = __expf(srow[j] - mx);
            srow[j] = e;
            sum += e;
        }
        #pragma unroll
        for (int o = 8; o; o >>= 1) sum += __shfl_xor_sync(0xffffffffu, sum, o);
        const float inv = 1.0f / sum;

        if (attn) {
            float* arow = attn + ((size_t)bh * S_ + (q0 + ty)) * S_;
            for (int j = tx; j < S_; j += 16) {
                float p = srow[j] * inv;
                srow[j] = p;
                arow[j] = p;        // coalesced streaming store
            }
        } else {
            for (int j = tx; j < S_; j += 16) srow[j] *= inv;
        }
    }
    __syncthreads();

    // ======================= Phase 3: out = P @ V (split-k x4) =======================
    {
        const int d4 = tid & 15;         // d = d4*4 .. d4*4+3
        const int qg = (tid >> 4) & 3;   // q group: rows qg*4 .. qg*4+3
        const int kp = tid >> 6;         // k partition 0..3 (32 k each per tile)

        float4 acc[4];
        #pragma unroll
        for (int qq = 0; qq < 4; ++qq) acc[qq] = make_float4(0.f, 0.f, 0.f, 0.f);

        for (int vt = 0; vt < NKT; ++vt) {
            __syncthreads();   // previous V tile fully consumed
            {
                const float4* src = (const float4*)(Vbh + (size_t)vt * KT * D_);
                #pragma unroll
                for (int t = 0; t < 8; ++t) {
                    int idx = tid + t * THREADS;
                    int r = idx >> 4, c4 = idx & 15;
                    *(float4*)(Ks + r * KROW + c4 * 4) = src[idx];
                }
            }
            __syncthreads();

            #pragma unroll 4
            for (int i = 0; i < 32; ++i) {
                const int kl = kp * 32 + i;
                float4 vv = *(const float4*)(Ks + kl * KROW + d4 * 4);
                #pragma unroll
                for (int qq = 0; qq < 4; ++qq) {
                    float p = Ss[(qg * 4 + qq) * S_ + vt * KT + kl]; // broadcast
                    acc[qq].x += p * vv.x;
                    acc[qq].y += p * vv.y;
                    acc[qq].z += p * vv.z;
                    acc[qq].w += p * vv.w;
                }
            }
        }

        // cross-partition reduction via smem (reuse Ks: 4 * 256 float4 = 16 KB)
        __syncthreads();
        float4* red = (float4*)Ks;
        #pragma unroll
        for (int qq = 0; qq < 4; ++qq)
            red[kp * 256 + (qg * 4 + qq) * 16 + d4] = acc[qq];
        __syncthreads();

        if (out) {
            // 256 threads, one (q, d4) pair each
            const int q  = tid >> 4;
            const int dd = tid & 15;
            float4 r0 = red[0 * 256 + q * 16 + dd];
            float4 r1 = red[1 * 256 + q * 16 + dd];
            float4 r2 = red[2 * 256 + q * 16 + dd];
            float4 r3 = red[3 * 256 + q * 16 + dd];
            float4 o;
            o.x = r0.x + r1.x + r2.x + r3.x;
            o.y = r0.y + r1.y + r2.y + r3.y;
            o.z = r0.z + r1.z + r2.z + r3.z;
            o.w = r0.w + r1.w + r2.w + r3.w;
            *(float4*)(out + ((size_t)bh * S_ + (q0 + q)) * D_ + dd * 4) = o;
        }
    }
}

extern "C" void kernel_launch(void* const* d_in, const int* in_sizes, int n_in,
                              void* d_out, int out_size)
{
    const float* Q    = (const float*)d_in[0];
    const float* K    = (const float*)d_in[1];
    const float* V    = (const float*)d_in[2];
    const int*   mask = (const int*)d_in[3];

    const size_t OUT_E  = (size_t)B_ * H_ * S_ * D_;   //   8388608
    const size_t ATTN_E = (size_t)B_ * H_ * S_ * S_;   // 268435456

    float* o = nullptr;
    float* a = nullptr;
    if ((size_t)out_size >= OUT_E + ATTN_E) {          // (out, attn) concatenated
        o = (float*)d_out;
        a = (float*)d_out + OUT_E;
    } else if ((size_t)out_size == ATTN_E) {           // only attn expected
        a = (float*)d_out;
    } else {                                           // only out expected
        o = (float*)d_out;
    }

    cudaFuncSetAttribute(attn_fused, cudaFuncAttributeMaxDynamicSharedMemorySize, SMEM_BYTES);

    dim3 grid(B_ * H_, S_ / QT);
    attn_fused<<<grid, THREADS, SMEM_BYTES>>>(Q, K, V, mask, o, a);
}

// round 4
// speedup vs baseline: 2.9549x; 2.9548x over previous
#include <cuda_runtime.h>
#include <cuda_fp16.h>

typedef unsigned int u32;

#define B_ 4
#define H_ 16
#define S_ 2048
#define D_ 64
#define NKT 16
#define THREADS 256
#define KQ_STR 36      // u32 per K/Q smem row (72 halves, conflict-free frag loads)
#define VT_STR 65      // u32 per Vt smem row (130 halves)
#define AB_STR 68      // floats per abuf row
#define UNI (1.0f / 2048.0f)

__device__ u32 g_mbits[(size_t)B_ * S_ * (S_ / 32)];   // 2 MB mask bitfield

// smem byte offsets
#define SM_QHI  0
#define SM_QLO  (SM_QHI  + 128 * KQ_STR * 4)
#define SM_KHI  (SM_QLO  + 128 * KQ_STR * 4)
#define SM_KLO  (SM_KHI  + 128 * KQ_STR * 4)
#define SM_VTHI (SM_KLO  + 128 * KQ_STR * 4)
#define SM_VTLO (SM_VTHI + 64 * VT_STR * 4)
#define SM_ABUF (SM_VTLO + 64 * VT_STR * 4)
#define SMEM_BYTES (SM_ABUF + 8 * 16 * AB_STR * 4)     // 141824 B

__device__ __forceinline__ void mma16816(float c[4], const u32 a[4], u32 b0, u32 b1) {
    asm volatile("mma.sync.aligned.m16n8k16.row.col.f32.f16.f16.f32 "
                 "{%0,%1,%2,%3}, {%4,%5,%6,%7}, {%8,%9}, {%0,%1,%2,%3};"
                 : "+f"(c[0]), "+f"(c[1]), "+f"(c[2]), "+f"(c[3])
                 : "r"(a[0]), "r"(a[1]), "r"(a[2]), "r"(a[3]), "r"(b0), "r"(b1));
}

// split (x,y) into packed fp16 hi pair and fp16 residual-lo pair
__device__ __forceinline__ void split2(float x, float y, u32& h, u32& l) {
    __half hx = __float2half_rn(x), hy = __float2half_rn(y);
    __half lx = __float2half_rn(x - __half2float(hx));
    __half ly = __float2half_rn(y - __half2float(hy));
    __half2 H = __halves2half2(hx, hy), L = __halves2half2(lx, ly);
    h = *reinterpret_cast<u32*>(&H);
    l = *reinterpret_cast<u32*>(&L);
}

// stage 128x64 fp32 row-major -> hi/lo fp16 smem [128][KQ_STR u32]
__device__ __forceinline__ void stage_kq(const float* __restrict__ src,
                                         u32* hi, u32* lo, int tid, float scale) {
    const float4* s4 = (const float4*)src;
    #pragma unroll
    for (int it = 0; it < 8; ++it) {
        int idx = it * THREADS + tid;
        int r = idx >> 4, c4 = idx & 15;
        float4 v = s4[idx];
        v.x *= scale; v.y *= scale; v.z *= scale; v.w *= scale;
        u32 h0, l0, h1, l1;
        split2(v.x, v.y, h0, l0);
        split2(v.z, v.w, h1, l1);
        int o = r * KQ_STR + c4 * 2;
        hi[o] = h0; hi[o + 1] = h1;
        lo[o] = l0; lo[o + 1] = l1;
    }
}

// stage 128x64 fp32 V row-major -> transposed hi/lo fp16 smem Vt[64 d][VT_STR u32]
// u32 at Vt[d][kp] = { V[2kp][d] (lo half), V[2kp+1][d] (hi half) }
__device__ __forceinline__ void stage_vt(const float* __restrict__ src,
                                         u32* hi, u32* lo, int tid) {
    const float4* s4 = (const float4*)src;
    #pragma unroll
    for (int it = 0; it < 4; ++it) {
        int idx = it * THREADS + tid;
        int d4 = idx & 15, kp = idx >> 4;          // kp 0..63
        float4 a = s4[(2 * kp) * 16 + d4];
        float4 b = s4[(2 * kp + 1) * 16 + d4];
        float av[4] = {a.x, a.y, a.z, a.w};
        float bv[4] = {b.x, b.y, b.z, b.w};
        #pragma unroll
        for (int dd = 0; dd < 4; ++dd) {
            u32 h, l;
            split2(av[dd], bv[dd], h, l);
            hi[(4 * d4 + dd) * VT_STR + kp] = h;
            lo[(4 * d4 + dd) * VT_STR + kp] = l;
        }
    }
}

__global__ void maskbits_kernel(const int* __restrict__ mask) {
    int w = blockIdx.x * blockDim.x + threadIdx.x;
    const int4* src = (const int4*)mask + (size_t)w * 8;
    u32 bits = 0;
    #pragma unroll
    for (int i = 0; i < 8; ++i) {
        int4 v = src[i];
        bits |= (v.x != 0 ? 1u : 0u) << (i * 4);
        bits |= (v.y != 0 ? 1u : 0u) << (i * 4 + 1);
        bits |= (v.z != 0 ? 1u : 0u) << (i * 4 + 2);
        bits |= (v.w != 0 ? 1u : 0u) << (i * 4 + 3);
    }
    g_mbits[w] = bits;
}

__global__ __launch_bounds__(THREADS, 1)
void attn_mma(const float* __restrict__ Q, const float* __restrict__ K,
              const float* __restrict__ V, float* __restrict__ outp,
              float* __restrict__ attn)
{
    extern __shared__ char sm[];
    u32* QHI  = (u32*)(sm + SM_QHI);
    u32* QLO  = (u32*)(sm + SM_QLO);
    u32* KHI  = (u32*)(sm + SM_KHI);
    u32* KLO  = (u32*)(sm + SM_KLO);
    u32* VTHI = (u32*)(sm + SM_VTHI);
    u32* VTLO = (u32*)(sm + SM_VTLO);

    const int tid = threadIdx.x, wid = tid >> 5, lane = tid & 31;
    const int g = lane >> 2, i = lane & 3;        // fragment row-group / col-group
    const int bh = blockIdx.x, b = bh >> 4, q0 = blockIdx.y * 128;
    const int qw = wid * 16;                      // warp's q-row base within tile

    float* abuf = (float*)(sm + SM_ABUF) + wid * 16 * AB_STR;

    const float* Qb = Q + ((size_t)bh * S_ + q0) * D_;
    const float* Kb = K + (size_t)bh * S_ * D_;
    const float* Vb = V + (size_t)bh * S_ * D_;

    stage_kq(Qb, QHI, QLO, tid, 0.125f);          // fold 1/sqrt(64)
    __syncthreads();

    // preload Q fragments (rows qw+g, qw+g+8; all 4 d-chunks), hi and lo
    u32 qh[4][4], ql[4][4];
    {
        const int rA = (qw + g) * KQ_STR, rB = (qw + g + 8) * KQ_STR;
        #pragma unroll
        for (int kc = 0; kc < 4; ++kc) {
            int o = kc * 8 + i;
            qh[kc][0] = QHI[rA + o];     qh[kc][1] = QHI[rB + o];
            qh[kc][2] = QHI[rA + o + 4]; qh[kc][3] = QHI[rB + o + 4];
            ql[kc][0] = QLO[rA + o];     ql[kc][1] = QLO[rB + o];
            ql[kc][2] = QLO[rA + o + 4]; ql[kc][3] = QLO[rB + o + 4];
        }
    }

    const u32* mra = g_mbits + (size_t)(b * S_ + q0 + qw + g) * (S_ / 32);
    const u32* mrb = mra + 8 * (S_ / 32);

    float sa = 0.f, sb = 0.f;

    // =================== PASS 1: QK^T + row sums of exp ===================
    for (int kt = 0; kt < NKT; ++kt) {
        __syncthreads();
        stage_kq(Kb + (size_t)kt * 128 * D_, KHI, KLO, tid, 1.f);
        __syncthreads();

        #pragma unroll
        for (int sub = 0; sub < 2; ++sub) {
            float c[8][4];
            #pragma unroll
            for (int j = 0; j < 8; ++j)
                c[j][0] = c[j][1] = c[j][2] = c[j][3] = 0.f;

            #pragma unroll
            for (int j = 0; j < 8; ++j) {
                int kbase = (sub * 64 + j * 8 + g) * KQ_STR + i;
                #pragma unroll
                for (int kc = 0; kc < 4; ++kc) {
                    u32 bh0 = KHI[kbase + kc * 8], bh1 = KHI[kbase + kc * 8 + 4];
                    u32 bl0 = KLO[kbase + kc * 8], bl1 = KLO[kbase + kc * 8 + 4];
                    mma16816(c[j], qh[kc], bh0, bh1);
                    mma16816(c[j], qh[kc], bl0, bl1);
                    mma16816(c[j], ql[kc], bh0, bh1);
                }
            }

            u32 ma0 = mra[kt * 4 + sub * 2], ma1 = mra[kt * 4 + sub * 2 + 1];
            u32 mb0 = mrb[kt * 4 + sub * 2], mb1 = mrb[kt * 4 + sub * 2 + 1];
            #pragma unroll
            for (int j = 0; j < 8; ++j) {
                int sh = 8 * (j & 3) + 2 * i;
                u32 wa = ((j < 4) ? ma0 : ma1) >> sh;
                u32 wb = ((j < 4) ? mb0 : mb1) >> sh;
                if (wa & 1u) sa += __expf(c[j][0]);
                if (wa & 2u) sa += __expf(c[j][1]);
                if (wb & 1u) sb += __expf(c[j][2]);
                if (wb & 2u) sb += __expf(c[j][3]);
            }
        }
    }
    sa += __shfl_xor_sync(0xffffffffu, sa, 1);
    sa += __shfl_xor_sync(0xffffffffu, sa, 2);
    sb += __shfl_xor_sync(0xffffffffu, sb, 1);
    sb += __shfl_xor_sync(0xffffffffu, sb, 2);
    const bool ua = (sa == 0.f), ub = (sb == 0.f);
    const float inva = ua ? 0.f : (1.0f / sa);
    const float invb = ub ? 0.f : (1.0f / sb);

    // =================== PASS 2: recompute, attn write, P@V ===================
    float o[8][4];
    #pragma unroll
    for (int d = 0; d < 8; ++d) o[d][0] = o[d][1] = o[d][2] = o[d][3] = 0.f;

    for (int kt = 0; kt < NKT; ++kt) {
        __syncthreads();
        stage_kq(Kb + (size_t)kt * 128 * D_, KHI, KLO, tid, 1.f);
        stage_vt(Vb + (size_t)kt * 128 * D_, VTHI, VTLO, tid);
        __syncthreads();

        #pragma unroll
        for (int sub = 0; sub < 2; ++sub) {
            float c[8][4];
            #pragma unroll
            for (int j = 0; j < 8; ++j)
                c[j][0] = c[j][1] = c[j][2] = c[j][3] = 0.f;

            #pragma unroll
            for (int j = 0; j < 8; ++j) {
                int kbase = (sub * 64 + j * 8 + g) * KQ_STR + i;
                #pragma unroll
                for (int kc = 0; kc < 4; ++kc) {
                    u32 bh0 = KHI[kbase + kc * 8], bh1 = KHI[kbase + kc * 8 + 4];
                    u32 bl0 = KLO[kbase + kc * 8], bl1 = KLO[kbase + kc * 8 + 4];
                    mma16816(c[j], qh[kc], bh0, bh1);
                    mma16816(c[j], qh[kc], bl0, bl1);
                    mma16816(c[j], ql[kc], bh0, bh1);
                }
            }

            u32 ma0 = mra[kt * 4 + sub * 2], ma1 = mra[kt * 4 + sub * 2 + 1];
            u32 mb0 = mrb[kt * 4 + sub * 2], mb1 = mrb[kt * 4 + sub * 2 + 1];
            #pragma unroll
            for (int j = 0; j < 8; ++j) {
                int sh = 8 * (j & 3) + 2 * i;
                u32 wa = ((j < 4) ? ma0 : ma1) >> sh;
                u32 wb = ((j < 4) ? mb0 : mb1) >> sh;
                float p0 = (wa & 1u) ? __expf(c[j][0]) * inva : 0.f;
                float p1 = (wa & 2u) ? __expf(c[j][1]) * inva : 0.f;
                float p2 = (wb & 1u) ? __expf(c[j][2]) * invb : 0.f;
                float p3 = (wb & 2u) ? __expf(c[j][3]) * invb : 0.f;
                if (ua) { p0 = UNI; p1 = UNI; }
                if (ub) { p2 = UNI; p3 = UNI; }
                c[j][0] = p0; c[j][1] = p1; c[j][2] = p2; c[j][3] = p3;
            }

            // coalesced attn write through warp-private smem transpose
            if (attn) {
                #pragma unroll
                for (int j = 0; j < 8; ++j) {
                    *(float2*)&abuf[g * AB_STR + 8 * j + 2 * i]       = make_float2(c[j][0], c[j][1]);
                    *(float2*)&abuf[(g + 8) * AB_STR + 8 * j + 2 * i] = make_float2(c[j][2], c[j][3]);
                }
                __syncwarp();
                const int r2 = lane >> 4, c4 = lane & 15;
                #pragma unroll
                for (int rr = 0; rr < 8; ++rr) {
                    int row = rr * 2 + r2;
                    float4 v = *(float4*)&abuf[row * AB_STR + c4 * 4];
                    *(float4*)&attn[((size_t)bh * S_ + q0 + qw + row) * S_
                                    + (size_t)kt * 128 + sub * 64 + c4 * 4] = v;
                }
                __syncwarp();
            }

            // pack P fragments from score registers (no smem round trip)
            u32 ah[4][4], al[4][4];
            #pragma unroll
            for (int kc = 0; kc < 4; ++kc) {
                split2(c[2 * kc][0],     c[2 * kc][1],     ah[kc][0], al[kc][0]);
                split2(c[2 * kc][2],     c[2 * kc][3],     ah[kc][1], al[kc][1]);
                split2(c[2 * kc + 1][0], c[2 * kc + 1][1], ah[kc][2], al[kc][2]);
                split2(c[2 * kc + 1][2], c[2 * kc + 1][3], ah[kc][3], al[kc][3]);
            }
            #pragma unroll
            for (int dblk = 0; dblk < 8; ++dblk) {
                int vb = (dblk * 8 + g) * VT_STR + sub * 32 + i;
                #pragma unroll
                for (int kc = 0; kc < 4; ++kc) {
                    u32 vh0 = VTHI[vb + kc * 8], vh1 = VTHI[vb + kc * 8 + 4];
                    u32 vl0 = VTLO[vb + kc * 8], vl1 = VTLO[vb + kc * 8 + 4];
                    mma16816(o[dblk], ah[kc], vh0, vh1);
                    mma16816(o[dblk], al[kc], vh0, vh1);
                    mma16816(o[dblk], ah[kc], vl0, vl1);
                }
            }
        }
    }

    // =================== epilogue: write out ===================
    if (outp) {
        #pragma unroll
        for (int dblk = 0; dblk < 8; ++dblk) {
            *(float2*)&abuf[g * AB_STR + 8 * dblk + 2 * i]       = make_float2(o[dblk][0], o[dblk][1]);
            *(float2*)&abuf[(g + 8) * AB_STR + 8 * dblk + 2 * i] = make_float2(o[dblk][2], o[dblk][3]);
        }
        __syncwarp();
        const int r2 = lane >> 4, c4 = lane & 15;
        #pragma unroll
        for (int rr = 0; rr < 8; ++rr) {
            int row = rr * 2 + r2;
            float4 v = *(float4*)&abuf[row * AB_STR + c4 * 4];
            *(float4*)&outp[((size_t)bh * S_ + q0 + qw + row) * D_ + c4 * 4] = v;
        }
    }
}

extern "C" void kernel_launch(void* const* d_in, const int* in_sizes, int n_in,
                              void* d_out, int out_size)
{
    const float* Q    = (const float*)d_in[0];
    const float* K    = (const float*)d_in[1];
    const float* V    = (const float*)d_in[2];
    const int*   mask = (const int*)d_in[3];

    const size_t OUT_E  = (size_t)B_ * H_ * S_ * D_;
    const size_t ATTN_E = (size_t)B_ * H_ * S_ * S_;
    float* o = nullptr; float* a = nullptr;
    if ((size_t)out_size >= OUT_E + ATTN_E) { o = (float*)d_out; a = (float*)d_out + OUT_E; }
    else if ((size_t)out_size == ATTN_E)    { a = (float*)d_out; }
    else                                    { o = (float*)d_out; }

    maskbits_kernel<<<(B_ * S_ * (S_ / 32)) / 256, 256>>>(mask);

    cudaFuncSetAttribute(attn_mma, cudaFuncAttributeMaxDynamicSharedMemorySize, SMEM_BYTES);
    dim3 grid(B_ * H_, S_ / 128);
    attn_mma<<<grid, THREADS, SMEM_BYTES>>>(Q, K, V, o, a);
}